// round 13
// baseline (speedup 1.0000x reference)
#include <cuda_runtime.h>
#include <cuda_bf16.h>

#define N_NODES 10000
#define N_EDGES 640000
#define F_IN 128
#define F_H 128
#define F_OUT 64

// ---------------- scratch (device globals; zero-initialized at load) -----------
__device__ int   g_deg_in [N_NODES];     // re-zeroed by k_scan_rsqrt each call
__device__ int   g_deg_out[N_NODES];     // re-zeroed by k_scan_rsqrt each call
__device__ float g_rs_in  [N_NODES];
__device__ float g_rs_out [N_NODES];
__device__ int   g_row_ptr[N_NODES + 1];
__device__ long long g_pack[N_EDGES];    // s | d<<14 | rank<<28
__device__ int   g_src_sorted[N_EDGES];
__device__ __align__(16) __nv_bfloat162 g_A1b[N_NODES * F_H / 2];   // (X@W1)*rs_out, bf16
__device__ __align__(16) float          g_H  [N_NODES * F_H];       // layer-1 out (fp32)
__device__ __align__(16) __nv_bfloat162 g_A2b[N_NODES * F_OUT / 2]; // (H@W2)*rs_out, bf16

// ---------------- degrees + rank + packed record (inline dtype detect) ---------
__global__ void k_degrees(const int* __restrict__ src,
                          const int* __restrict__ dst) {
    __shared__ int s_i32;
    if (threadIdx.x < 32) {
        // sample first 32 "high words" of candidate int64 layout (<=65 ints, safe)
        int v = src[2 * threadIdx.x + 1];
        #pragma unroll
        for (int o = 16; o; o >>= 1) v |= __shfl_xor_sync(0xFFFFFFFFu, v, o);
        if (threadIdx.x == 0) s_i32 = (v != 0) ? 1 : 0;
    }
    __syncthreads();
    const int i32 = s_i32;
    int e = blockIdx.x * 256 + threadIdx.x;
    if (e < N_EDGES) {
        int s = i32 ? src[e] : src[2 * e];
        int d = i32 ? dst[e] : dst[2 * e];
        atomicAdd(&g_deg_out[s], 1);                 // no return -> REDG
        int rank = atomicAdd(&g_deg_in[d], 1);       // return = rank in row
        g_pack[e] = (long long)s | ((long long)d << 14) | ((long long)rank << 28);
    }
}

// ---------------- fused: rsqrt + single-pass exclusive scan + re-zero -----------
__global__ void k_scan_rsqrt() {
    constexpr int PT = 10;   // 1024*10 >= 10000
    const int tid  = threadIdx.x;
    const int lane = tid & 31, warp = tid >> 5;

    for (int i = tid; i < N_NODES; i += 1024) {
        g_rs_in [i] = rsqrtf((float)max(g_deg_in [i], 1));
        g_rs_out[i] = rsqrtf((float)max(g_deg_out[i], 1));
    }

    int base = tid * PT;
    int v[PT];
    int tot = 0;
    #pragma unroll
    for (int j = 0; j < PT; j++) {
        int i = base + j;
        v[j] = (i < N_NODES) ? g_deg_in[i] : 0;
        tot += v[j];
    }

    __shared__ int wsum[32];
    int x = tot;
    #pragma unroll
    for (int o = 1; o < 32; o <<= 1) {
        int t = __shfl_up_sync(0xFFFFFFFFu, x, o);
        if (lane >= o) x += t;
    }
    if (lane == 31) wsum[warp] = x;
    __syncthreads();
    if (warp == 0) {
        int w = wsum[lane];
        #pragma unroll
        for (int o = 1; o < 32; o <<= 1) {
            int t = __shfl_up_sync(0xFFFFFFFFu, w, o);
            if (lane >= o) w += t;
        }
        wsum[lane] = w;
    }
    __syncthreads();
    int excl = (x - tot) + (warp ? wsum[warp - 1] : 0);

    if (tid == 0) g_row_ptr[0] = 0;
    int run = excl;
    #pragma unroll
    for (int j = 0; j < PT; j++) {
        int i = base + j;
        run += v[j];
        if (i < N_NODES) g_row_ptr[i + 1] = run;
    }

    __syncthreads();
    for (int i = tid; i < N_NODES; i += 1024) {
        g_deg_in[i] = 0; g_deg_out[i] = 0;
    }
}

// ---------------- fill: one packed load, atomic-free scatter --------------------
__global__ void k_fill() {
    int e = blockIdx.x * 256 + threadIdx.x;
    if (e < N_EDGES) {
        long long w = g_pack[e];
        int s    = (int)(w & 0x3FFF);
        int d    = (int)((w >> 14) & 0x3FFF);
        int rank = (int)(w >> 28);
        g_src_sorted[g_row_ptr[d] + rank] = s;
    }
}

// ---------------- GEMM1: 10000x128x128, BM=64, BN=128, BK=16, 4x8/thread -------
// C = (X@W1)*rs_out as bf16 pairs. 256 threads, grid (1, 157).
__global__ void k_gemm1(const float* __restrict__ A, const float* __restrict__ B) {
    __shared__ __align__(16) float As[16][68];    // [BK][BM+4]
    __shared__ __align__(16) float Bs[16][128];
    const int tid = threadIdx.x;
    const int tx = tid & 15;          // 16 col-groups * 8 cols = 128
    const int ty = tid >> 4;          // 16 row-groups * 4 rows = 64
    const int bm = blockIdx.y * 64;
    const int M = N_NODES, K = F_IN;  // N = 128
    unsigned long long acc2[4][4] = {};

    for (int k0 = 0; k0 < K; k0 += 16) {
        {
            int r = tid >> 2;
            int c = (tid & 3) * 4;
            float4 v = make_float4(0.f, 0.f, 0.f, 0.f);
            if (bm + r < M)
                v = *reinterpret_cast<const float4*>(&A[(size_t)(bm + r) * K + k0 + c]);
            As[c + 0][r] = v.x; As[c + 1][r] = v.y;
            As[c + 2][r] = v.z; As[c + 3][r] = v.w;
        }
        {
            #pragma unroll
            for (int h = 0; h < 2; h++) {
                int idx = tid + h * 256;       // 512 float4 total
                int r  = idx >> 5;             // 0..15
                int c4 = (idx & 31) * 4;       // 0..124
                float4 v = *reinterpret_cast<const float4*>(&B[(size_t)(k0 + r) * 128 + c4]);
                Bs[r][c4 + 0] = v.x; Bs[r][c4 + 1] = v.y;
                Bs[r][c4 + 2] = v.z; Bs[r][c4 + 3] = v.w;
            }
        }
        __syncthreads();
        #pragma unroll
        for (int k = 0; k < 16; k++) {
            float4 a = *reinterpret_cast<const float4*>(&As[k][ty * 4]);
            ulonglong2 b0 = *reinterpret_cast<const ulonglong2*>(&Bs[k][tx * 8]);
            ulonglong2 b1 = *reinterpret_cast<const ulonglong2*>(&Bs[k][tx * 8 + 4]);
            float av[4] = {a.x, a.y, a.z, a.w};
            #pragma unroll
            for (int i = 0; i < 4; i++) {
                unsigned long long ap;
                asm("mov.b64 %0, {%1, %1};" : "=l"(ap) : "f"(av[i]));
                asm("fma.rn.f32x2 %0, %1, %2, %0;" : "+l"(acc2[i][0]) : "l"(ap), "l"(b0.x));
                asm("fma.rn.f32x2 %0, %1, %2, %0;" : "+l"(acc2[i][1]) : "l"(ap), "l"(b0.y));
                asm("fma.rn.f32x2 %0, %1, %2, %0;" : "+l"(acc2[i][2]) : "l"(ap), "l"(b1.x));
                asm("fma.rn.f32x2 %0, %1, %2, %0;" : "+l"(acc2[i][3]) : "l"(ap), "l"(b1.y));
            }
        }
        __syncthreads();
    }
    // epilogue: 8 cols per thread -> 4 bf16x2 -> one uint4 store
    #pragma unroll
    for (int i = 0; i < 4; i++) {
        int m = bm + ty * 4 + i;
        if (m < M) {
            float s = g_rs_out[m];
            uint4 pk;
            #pragma unroll
            for (int j = 0; j < 4; j++) {
                float c0, c1;
                asm("mov.b64 {%0, %1}, %2;" : "=f"(c0), "=f"(c1) : "l"(acc2[i][j]));
                __nv_bfloat162 p = __float22bfloat162_rn(make_float2(c0 * s, c1 * s));
                (&pk.x)[j] = *reinterpret_cast<unsigned int*>(&p);
            }
            *reinterpret_cast<uint4*>(&g_A1b[(size_t)m * 64 + tx * 4]) = pk;
        }
    }
}

// ---------------- GEMM2 body (256 thr, BM=BN=64, BK=16, 4x4, FFMA2 inner) -----
__global__ void k_gemm2(const float* __restrict__ W2) {
    const float* __restrict__ A = &g_H[0];
    const float* __restrict__ B = W2;
    __nv_bfloat162* __restrict__ C2 = &g_A2b[0];
    const int M = N_NODES, N = F_OUT, K = F_H;
    __shared__ __align__(16) float As[16][68];
    __shared__ __align__(16) float Bs[16][64];
    int tid = threadIdx.x;
    int tx = tid & 15, ty = tid >> 4;
    int bm = blockIdx.y * 64;
    int bn = blockIdx.x * 64;
    unsigned long long acc2[4][2] = {};
    for (int k0 = 0; k0 < K; k0 += 16) {
        {
            int r = tid >> 2;
            int c = (tid & 3) * 4;
            float4 v = make_float4(0.f, 0.f, 0.f, 0.f);
            if (bm + r < M)
                v = *reinterpret_cast<const float4*>(&A[(size_t)(bm + r) * K + k0 + c]);
            As[c + 0][r] = v.x; As[c + 1][r] = v.y;
            As[c + 2][r] = v.z; As[c + 3][r] = v.w;
        }
        {
            int r = tid >> 4;
            int c = (tid & 15) * 4;
            float4 v = *reinterpret_cast<const float4*>(&B[(size_t)(k0 + r) * N + bn + c]);
            Bs[r][c + 0] = v.x; Bs[r][c + 1] = v.y;
            Bs[r][c + 2] = v.z; Bs[r][c + 3] = v.w;
        }
        __syncthreads();
        #pragma unroll
        for (int k = 0; k < 16; k++) {
            float4 a = *reinterpret_cast<const float4*>(&As[k][ty * 4]);
            ulonglong2 bp = *reinterpret_cast<const ulonglong2*>(&Bs[k][tx * 4]);
            float av[4] = {a.x, a.y, a.z, a.w};
            #pragma unroll
            for (int i = 0; i < 4; i++) {
                unsigned long long ap;
                asm("mov.b64 %0, {%1, %1};" : "=l"(ap) : "f"(av[i]));
                asm("fma.rn.f32x2 %0, %1, %2, %0;" : "+l"(acc2[i][0]) : "l"(ap), "l"(bp.x));
                asm("fma.rn.f32x2 %0, %1, %2, %0;" : "+l"(acc2[i][1]) : "l"(ap), "l"(bp.y));
            }
        }
        __syncthreads();
    }
    const int NC = N / 2;
    #pragma unroll
    for (int i = 0; i < 4; i++) {
        int m = bm + ty * 4 + i;
        if (m < M) {
            float s = g_rs_out[m];
            float c0, c1, c2, c3;
            asm("mov.b64 {%0, %1}, %2;" : "=f"(c0), "=f"(c1) : "l"(acc2[i][0]));
            asm("mov.b64 {%0, %1}, %2;" : "=f"(c2), "=f"(c3) : "l"(acc2[i][1]));
            __nv_bfloat162 p0 = __float22bfloat162_rn(make_float2(c0 * s, c1 * s));
            __nv_bfloat162 p1 = __float22bfloat162_rn(make_float2(c2 * s, c3 * s));
            uint2 pk;
            pk.x = *reinterpret_cast<unsigned int*>(&p0);
            pk.y = *reinterpret_cast<unsigned int*>(&p1);
            *reinterpret_cast<uint2*>(&C2[(size_t)m * NC + (bn >> 1) + tx * 2]) = pk;
        }
    }
}

// ---------------- SpMM (CSR gather over bf16x2 lanes, fp32 accumulate) --------
template <int F, bool RELU>
__device__ __forceinline__ void spmm_bf_body(const __nv_bfloat162* __restrict__ X2,
                                             const float* __restrict__ bias,
                                             float* __restrict__ out)
{
    constexpr int T = F / 2;
    const int row = blockIdx.x;
    const int t   = threadIdx.x;
    const int beg = g_row_ptr[row];
    const int end = g_row_ptr[row + 1];
    __shared__ int sidx[256];
    float2 a0 = {0.f, 0.f}, a1 = {0.f, 0.f}, a2 = {0.f, 0.f}, a3 = {0.f, 0.f};
    for (int base = beg; base < end; base += 256) {
        int cnt = min(256, end - base);
        for (int i = t; i < cnt; i += T) sidx[i] = g_src_sorted[base + i];
        __syncthreads();
        int i = 0;
        for (; i + 4 <= cnt; i += 4) {
            float2 v0 = __bfloat1622float2(X2[(size_t)sidx[i + 0] * T + t]);
            float2 v1 = __bfloat1622float2(X2[(size_t)sidx[i + 1] * T + t]);
            float2 v2 = __bfloat1622float2(X2[(size_t)sidx[i + 2] * T + t]);
            float2 v3 = __bfloat1622float2(X2[(size_t)sidx[i + 3] * T + t]);
            a0.x += v0.x; a0.y += v0.y;
            a1.x += v1.x; a1.y += v1.y;
            a2.x += v2.x; a2.y += v2.y;
            a3.x += v3.x; a3.y += v3.y;
        }
        for (; i < cnt; i++) {
            float2 v = __bfloat1622float2(X2[(size_t)sidx[i] * T + t]);
            a0.x += v.x; a0.y += v.y;
        }
        __syncthreads();
    }
    float r = g_rs_in[row];
    float2 b = reinterpret_cast<const float2*>(bias)[t];
    float2 o;
    o.x = (a0.x + a1.x + a2.x + a3.x) * r + b.x;
    o.y = (a0.y + a1.y + a2.y + a3.y) * r + b.y;
    if (RELU) { o.x = fmaxf(o.x, 0.f); o.y = fmaxf(o.y, 0.f); }
    reinterpret_cast<float2*>(out)[(size_t)row * T + t] = o;
}

__global__ void k_spmm1(const float* __restrict__ b1) {
    spmm_bf_body<F_H, true>(&g_A1b[0], b1, &g_H[0]);
}
__global__ void k_spmm2(const float* __restrict__ b2, float* __restrict__ out) {
    spmm_bf_body<F_OUT, false>(&g_A2b[0], b2, out);
}

// ---------------- launch ----------------
extern "C" void kernel_launch(void* const* d_in, const int* in_sizes, int n_in,
                              void* d_out, int out_size) {
    const float* X   = (const float*)d_in[0];
    const int*   src = (const int*)d_in[1];   // int32 or int64 (device-detected)
    const int*   dst = (const int*)d_in[2];
    const float* W1  = (const float*)d_in[3];
    const float* b1  = (const float*)d_in[4];
    const float* W2  = (const float*)d_in[5];
    const float* b2  = (const float*)d_in[6];
    float* out = (float*)d_out;

    static cudaStream_t s2 = nullptr;
    static cudaEvent_t  ev_fork = nullptr, ev_join = nullptr;
    if (s2 == nullptr) {
        cudaStreamCreateWithFlags(&s2, cudaStreamNonBlocking);
        cudaEventCreateWithFlags(&ev_fork, cudaEventDisableTiming);
        cudaEventCreateWithFlags(&ev_join, cudaEventDisableTiming);
    }

    const int NB_EDGE = (N_EDGES + 255) / 256;   // 2500

    k_degrees   <<<NB_EDGE, 256>>>(src, dst);
    k_scan_rsqrt<<<1, 1024>>>();

    // fork AFTER scan: gemm1 (s2) runs concurrently with fill (main) only
    cudaEventRecord(ev_fork, 0);
    cudaStreamWaitEvent(s2, ev_fork, 0);
    dim3 grid1(1, (N_NODES + 63) / 64);          // 157 blocks
    k_gemm1<<<grid1, 256, 0, s2>>>(X, W1);
    cudaEventRecord(ev_join, s2);

    k_fill<<<NB_EDGE, 256>>>();

    cudaStreamWaitEvent(0, ev_join, 0);
    k_spmm1<<<N_NODES, F_H / 2>>>(b1);

    dim3 grid2(1, (N_NODES + 63) / 64);
    k_gemm2<<<grid2, 256>>>(W2);
    k_spmm2<<<N_NODES, F_OUT / 2>>>(b2, out);
}

// round 14
// speedup vs baseline: 1.1269x; 1.1269x over previous
#include <cuda_runtime.h>
#include <cuda_bf16.h>

#define N_NODES 10000
#define N_EDGES 640000
#define F_IN 128
#define F_H 128
#define F_OUT 64

// ---------------- scratch (device globals; zero-initialized at load) -----------
__device__ int   g_deg_in [N_NODES];     // re-zeroed by k_scan_rsqrt each call
__device__ int   g_deg_out[N_NODES];     // re-zeroed by k_scan_rsqrt each call
__device__ float g_rs_in  [N_NODES];
__device__ float g_rs_out [N_NODES];
__device__ int   g_row_ptr[N_NODES + 1];
__device__ long long g_pack[N_EDGES];    // s | d<<14 | rank<<28
__device__ int   g_src_sorted[N_EDGES];
__device__ __align__(16) __nv_bfloat162 g_A1b[N_NODES * F_H / 2];   // X@W1 (UNscaled), bf16
__device__ __align__(16) float          g_H  [N_NODES * F_H];       // layer-1 out (fp32)
__device__ __align__(16) __nv_bfloat162 g_A2b[N_NODES * F_OUT / 2]; // (H@W2)*rs_out, bf16

// ---------------- degrees + rank + packed record (inline dtype detect) ---------
__global__ void k_degrees(const int* __restrict__ src,
                          const int* __restrict__ dst) {
    __shared__ int s_i32;
    if (threadIdx.x < 32) {
        int v = src[2 * threadIdx.x + 1];
        #pragma unroll
        for (int o = 16; o; o >>= 1) v |= __shfl_xor_sync(0xFFFFFFFFu, v, o);
        if (threadIdx.x == 0) s_i32 = (v != 0) ? 1 : 0;
    }
    __syncthreads();
    const int i32 = s_i32;
    int e = blockIdx.x * 256 + threadIdx.x;
    if (e < N_EDGES) {
        int s = i32 ? src[e] : src[2 * e];
        int d = i32 ? dst[e] : dst[2 * e];
        atomicAdd(&g_deg_out[s], 1);                 // no return -> REDG
        int rank = atomicAdd(&g_deg_in[d], 1);       // return = rank in row
        g_pack[e] = (long long)s | ((long long)d << 14) | ((long long)rank << 28);
    }
}

// ---------------- fused: rsqrt + single-pass exclusive scan + re-zero -----------
__global__ void k_scan_rsqrt() {
    constexpr int PT = 10;   // 1024*10 >= 10000
    const int tid  = threadIdx.x;
    const int lane = tid & 31, warp = tid >> 5;

    for (int i = tid; i < N_NODES; i += 1024) {
        g_rs_in [i] = rsqrtf((float)max(g_deg_in [i], 1));
        g_rs_out[i] = rsqrtf((float)max(g_deg_out[i], 1));
    }

    int base = tid * PT;
    int v[PT];
    int tot = 0;
    #pragma unroll
    for (int j = 0; j < PT; j++) {
        int i = base + j;
        v[j] = (i < N_NODES) ? g_deg_in[i] : 0;
        tot += v[j];
    }

    __shared__ int wsum[32];
    int x = tot;
    #pragma unroll
    for (int o = 1; o < 32; o <<= 1) {
        int t = __shfl_up_sync(0xFFFFFFFFu, x, o);
        if (lane >= o) x += t;
    }
    if (lane == 31) wsum[warp] = x;
    __syncthreads();
    if (warp == 0) {
        int w = wsum[lane];
        #pragma unroll
        for (int o = 1; o < 32; o <<= 1) {
            int t = __shfl_up_sync(0xFFFFFFFFu, w, o);
            if (lane >= o) w += t;
        }
        wsum[lane] = w;
    }
    __syncthreads();
    int excl = (x - tot) + (warp ? wsum[warp - 1] : 0);

    if (tid == 0) g_row_ptr[0] = 0;
    int run = excl;
    #pragma unroll
    for (int j = 0; j < PT; j++) {
        int i = base + j;
        run += v[j];
        if (i < N_NODES) g_row_ptr[i + 1] = run;
    }

    __syncthreads();
    for (int i = tid; i < N_NODES; i += 1024) {
        g_deg_in[i] = 0; g_deg_out[i] = 0;
    }
}

// ---------------- fill: one packed load, atomic-free scatter --------------------
__global__ void k_fill() {
    int e = blockIdx.x * 256 + threadIdx.x;
    if (e < N_EDGES) {
        long long w = g_pack[e];
        int s    = (int)(w & 0x3FFF);
        int d    = (int)((w >> 14) & 0x3FFF);
        int rank = (int)(w >> 28);
        g_src_sorted[g_row_ptr[d] + rank] = s;
    }
}

// ---------------- GEMM body (256 thr, BM=BN=64, BK=16, 4x4, FFMA2 inner) ------
// SCALE=true: multiply rows by rs_out[m] before bf16 pack.
template <bool SCALE>
__device__ __forceinline__ void gemm_body_bf16(
    const float* __restrict__ A, const float* __restrict__ B,
    __nv_bfloat162* __restrict__ C2, int M, int N, int K)
{
    __shared__ __align__(16) float As[16][68];
    __shared__ __align__(16) float Bs[16][64];
    int tid = threadIdx.x;
    int tx = tid & 15, ty = tid >> 4;
    int bm = blockIdx.y * 64;
    int bn = blockIdx.x * 64;
    unsigned long long acc2[4][2] = {};
    for (int k0 = 0; k0 < K; k0 += 16) {
        {
            int r = tid >> 2;
            int c = (tid & 3) * 4;
            float4 v = make_float4(0.f, 0.f, 0.f, 0.f);
            if (bm + r < M)
                v = *reinterpret_cast<const float4*>(&A[(size_t)(bm + r) * K + k0 + c]);
            As[c + 0][r] = v.x; As[c + 1][r] = v.y;
            As[c + 2][r] = v.z; As[c + 3][r] = v.w;
        }
        {
            int r = tid >> 4;
            int c = (tid & 15) * 4;
            float4 v = *reinterpret_cast<const float4*>(&B[(size_t)(k0 + r) * N + bn + c]);
            Bs[r][c + 0] = v.x; Bs[r][c + 1] = v.y;
            Bs[r][c + 2] = v.z; Bs[r][c + 3] = v.w;
        }
        __syncthreads();
        #pragma unroll
        for (int k = 0; k < 16; k++) {
            float4 a = *reinterpret_cast<const float4*>(&As[k][ty * 4]);
            ulonglong2 bp = *reinterpret_cast<const ulonglong2*>(&Bs[k][tx * 4]);
            float av[4] = {a.x, a.y, a.z, a.w};
            #pragma unroll
            for (int i = 0; i < 4; i++) {
                unsigned long long ap;
                asm("mov.b64 %0, {%1, %1};" : "=l"(ap) : "f"(av[i]));
                asm("fma.rn.f32x2 %0, %1, %2, %0;" : "+l"(acc2[i][0]) : "l"(ap), "l"(bp.x));
                asm("fma.rn.f32x2 %0, %1, %2, %0;" : "+l"(acc2[i][1]) : "l"(ap), "l"(bp.y));
            }
        }
        __syncthreads();
    }
    const int NC = N / 2;
    #pragma unroll
    for (int i = 0; i < 4; i++) {
        int m = bm + ty * 4 + i;
        if (m < M) {
            float s = SCALE ? g_rs_out[m] : 1.0f;
            float c0, c1, c2, c3;
            asm("mov.b64 {%0, %1}, %2;" : "=f"(c0), "=f"(c1) : "l"(acc2[i][0]));
            asm("mov.b64 {%0, %1}, %2;" : "=f"(c2), "=f"(c3) : "l"(acc2[i][1]));
            __nv_bfloat162 p0 = __float22bfloat162_rn(make_float2(c0 * s, c1 * s));
            __nv_bfloat162 p1 = __float22bfloat162_rn(make_float2(c2 * s, c3 * s));
            uint2 pk;
            pk.x = *reinterpret_cast<unsigned int*>(&p0);
            pk.y = *reinterpret_cast<unsigned int*>(&p1);
            *reinterpret_cast<uint2*>(&C2[(size_t)m * NC + (bn >> 1) + tx * 2]) = pk;
        }
    }
}

__global__ void k_gemm1(const float* __restrict__ X, const float* __restrict__ W1) {
    gemm_body_bf16<false>(X, W1, &g_A1b[0], N_NODES, F_H, F_IN);   // UNscaled
}
__global__ void k_gemm2(const float* __restrict__ W2) {
    gemm_body_bf16<true>(&g_H[0], W2, &g_A2b[0], N_NODES, F_OUT, F_H);
}

// ---------------- SpMM (CSR gather over bf16x2 lanes, fp32 accumulate) --------
// EDGE_SCALE: multiply each gathered row by rs_out[src] (smem-staged, fp32 FMA).
template <int F, bool RELU, bool EDGE_SCALE>
__device__ __forceinline__ void spmm_bf_body(const __nv_bfloat162* __restrict__ X2,
                                             const float* __restrict__ bias,
                                             float* __restrict__ out)
{
    constexpr int T = F / 2;
    const int row = blockIdx.x;
    const int t   = threadIdx.x;
    const int beg = g_row_ptr[row];
    const int end = g_row_ptr[row + 1];
    __shared__ int sidx[256];
    __shared__ float srs[256];
    float2 a0 = {0.f, 0.f}, a1 = {0.f, 0.f}, a2 = {0.f, 0.f}, a3 = {0.f, 0.f};
    for (int base = beg; base < end; base += 256) {
        int cnt = min(256, end - base);
        for (int i = t; i < cnt; i += T) {
            int s = g_src_sorted[base + i];
            sidx[i] = s;
            if (EDGE_SCALE) srs[i] = g_rs_out[s];
        }
        __syncthreads();
        int i = 0;
        for (; i + 4 <= cnt; i += 4) {
            float2 v0 = __bfloat1622float2(X2[(size_t)sidx[i + 0] * T + t]);
            float2 v1 = __bfloat1622float2(X2[(size_t)sidx[i + 1] * T + t]);
            float2 v2 = __bfloat1622float2(X2[(size_t)sidx[i + 2] * T + t]);
            float2 v3 = __bfloat1622float2(X2[(size_t)sidx[i + 3] * T + t]);
            if (EDGE_SCALE) {
                float s0 = srs[i], s1 = srs[i + 1], s2 = srs[i + 2], s3 = srs[i + 3];
                a0.x += v0.x * s0; a0.y += v0.y * s0;
                a1.x += v1.x * s1; a1.y += v1.y * s1;
                a2.x += v2.x * s2; a2.y += v2.y * s2;
                a3.x += v3.x * s3; a3.y += v3.y * s3;
            } else {
                a0.x += v0.x; a0.y += v0.y;
                a1.x += v1.x; a1.y += v1.y;
                a2.x += v2.x; a2.y += v2.y;
                a3.x += v3.x; a3.y += v3.y;
            }
        }
        for (; i < cnt; i++) {
            float2 v = __bfloat1622float2(X2[(size_t)sidx[i] * T + t]);
            float sc = EDGE_SCALE ? srs[i] : 1.0f;
            a0.x += v.x * sc; a0.y += v.y * sc;
        }
        __syncthreads();
    }
    float r = g_rs_in[row];
    float2 b = reinterpret_cast<const float2*>(bias)[t];
    float2 o;
    o.x = (a0.x + a1.x + a2.x + a3.x) * r + b.x;
    o.y = (a0.y + a1.y + a2.y + a3.y) * r + b.y;
    if (RELU) { o.x = fmaxf(o.x, 0.f); o.y = fmaxf(o.y, 0.f); }
    reinterpret_cast<float2*>(out)[(size_t)row * T + t] = o;
}

__global__ void k_spmm1(const float* __restrict__ b1) {
    spmm_bf_body<F_H, true, true>(&g_A1b[0], b1, &g_H[0]);     // edge-scaled
}
__global__ void k_spmm2(const float* __restrict__ b2, float* __restrict__ out) {
    spmm_bf_body<F_OUT, false, false>(&g_A2b[0], b2, out);
}

// ---------------- launch ----------------
extern "C" void kernel_launch(void* const* d_in, const int* in_sizes, int n_in,
                              void* d_out, int out_size) {
    const float* X   = (const float*)d_in[0];
    const int*   src = (const int*)d_in[1];   // int32 or int64 (device-detected)
    const int*   dst = (const int*)d_in[2];
    const float* W1  = (const float*)d_in[3];
    const float* b1  = (const float*)d_in[4];
    const float* W2  = (const float*)d_in[5];
    const float* b2  = (const float*)d_in[6];
    float* out = (float*)d_out;

    static cudaStream_t s2 = nullptr;
    static cudaEvent_t  ev_fork = nullptr, ev_join = nullptr;
    if (s2 == nullptr) {
        cudaStreamCreateWithFlags(&s2, cudaStreamNonBlocking);
        cudaEventCreateWithFlags(&ev_fork, cudaEventDisableTiming);
        cudaEventCreateWithFlags(&ev_join, cudaEventDisableTiming);
    }

    const int NB_EDGE = (N_EDGES + 255) / 256;   // 2500

    // fork at the head: gemm1 (inputs only) runs alongside the whole CSR build
    cudaEventRecord(ev_fork, 0);
    cudaStreamWaitEvent(s2, ev_fork, 0);
    dim3 grid1(F_H / 64, (N_NODES + 63) / 64);   // (2, 157)
    k_gemm1<<<grid1, 256, 0, s2>>>(X, W1);
    cudaEventRecord(ev_join, s2);

    k_degrees   <<<NB_EDGE, 256>>>(src, dst);
    k_scan_rsqrt<<<1, 1024>>>();
    k_fill      <<<NB_EDGE, 256>>>();

    cudaStreamWaitEvent(0, ev_join, 0);
    k_spmm1<<<N_NODES, F_H / 2>>>(b1);

    dim3 grid2(F_OUT / 64, (N_NODES + 63) / 64); // (1, 157)
    k_gemm2<<<grid2, 256>>>(W2);
    k_spmm2<<<N_NODES, F_OUT / 2>>>(b2, out);
}